// round 1
// baseline (speedup 1.0000x reference)
#include <cuda_runtime.h>
#include <cstdint>
#include <cstddef>

// Problem constants
#define Bb 4
#define Ss 2048
#define Dd 1024
#define DI 2048          // D_INNER
#define NT (Bb*Ss)       // 8192 tokens
#define NE 8
#define RHID 128

// GEMM tile config
#define BM 128
#define BN 128
#define BKK 16
#define STR 20           // padded smem row stride (floats)

// Scratch (device globals: allocation-free rule)
__device__ float g_zx[(size_t)NT * (2*DI)];   // per-expert in_proj output, reused
__device__ float g_xact[(size_t)NT * DI];     // per-expert gated activation * comb
__device__ float g_comb[(size_t)NT * NE];     // routing combine weights

__device__ __forceinline__ float silu_(float x) { return x / (1.0f + expf(-x)); }

__device__ __forceinline__ uint32_t f2tf32(float f) {
    uint32_t u;
    asm("cvt.rna.tf32.f32 %0, %1;" : "=r"(u) : "f"(f));
    return u;
}

// ---------------------------------------------------------------------------
// Router: rh = silu(h @ W1^T); logits = rh @ W2^T; top-2 softmax -> comb[t][e]
// one block (128 threads) per token
// ---------------------------------------------------------------------------
__global__ void router_kernel(const float* __restrict__ h,
                              const float* __restrict__ w1,
                              const float* __restrict__ w2)
{
    int t = blockIdx.x;
    int j = threadIdx.x;                 // 0..127 hidden unit
    __shared__ float rh[RHID];
    __shared__ float logits[NE];

    const float4* h4 = reinterpret_cast<const float4*>(h + (size_t)t * Dd);
    const float4* w4 = reinterpret_cast<const float4*>(w1 + (size_t)j * Dd);
    float acc = 0.f;
#pragma unroll 8
    for (int i = 0; i < Dd / 4; ++i) {
        float4 a = h4[i], b = w4[i];
        acc += a.x*b.x + a.y*b.y + a.z*b.z + a.w*b.w;
    }
    rh[j] = silu_(acc);
    __syncthreads();

    if (j < NE) {
        const float* wr = w2 + j * RHID;
        float l = 0.f;
#pragma unroll
        for (int i = 0; i < RHID; ++i) l += rh[i] * wr[i];
        logits[j] = l;
    }
    __syncthreads();

    if (j == 0) {
        int i1 = 0; float l1 = logits[0];
#pragma unroll
        for (int e = 1; e < NE; ++e) if (logits[e] > l1) { l1 = logits[e]; i1 = e; }
        int i2 = -1; float l2 = -1e30f;
#pragma unroll
        for (int e = 0; e < NE; ++e) { if (e == i1) continue; if (logits[e] > l2) { l2 = logits[e]; i2 = e; } }
        // softmax over {l1,l2} == renormalized top-2 probs
        float wtop = 1.f / (1.f + expf(l2 - l1));
        float* cb = &g_comb[(size_t)t * NE];
#pragma unroll
        for (int e = 0; e < NE; ++e) cb[e] = 0.f;
        cb[i1] = wtop;
        cb[i2] = 1.f - wtop;
    }
}

// ---------------------------------------------------------------------------
// TF32 GEMM (TN): C[M,N] (+)= A[M,K] * W[N,K]^T. All fp32 in gmem.
// 128x128x16 tiles, double-buffered cp.async, 8 warps (2m x 4n), 64x32/warp.
// ---------------------------------------------------------------------------
__global__ __launch_bounds__(256, 2) void gemm_tn(
    const float* __restrict__ A, const float* __restrict__ W, float* __restrict__ C,
    int M, int N, int K, int accumulate)
{
    __shared__ float As[2][BM * STR];
    __shared__ float Bs[2][BN * STR];

    const int tid  = threadIdx.x;
    const int lane = tid & 31;
    const int warp = tid >> 5;
    const int g  = lane >> 2;   // group id 0..7
    const int tg = lane & 3;    // thread-in-group 0..3
    const int wm = (warp & 1) * 64;
    const int wn = (warp >> 1) * 32;

    const float* Ag = A + (size_t)(blockIdx.y * BM) * K;
    const float* Bg = W + (size_t)(blockIdx.x * BN) * K;

    float c[4][4][4];
#pragma unroll
    for (int i = 0; i < 4; ++i)
#pragma unroll
        for (int j = 0; j < 4; ++j)
#pragma unroll
            for (int r = 0; r < 4; ++r) c[i][j][r] = 0.f;

    const int nk = K / BKK;

    auto load_tile = [&](int buf, int kc) {
        const int k0 = kc * BKK;
#pragma unroll
        for (int i = 0; i < 2; ++i) {
            int idx = tid + i * 256;
            int row = idx >> 2, c4 = idx & 3;
            const float* src = Ag + (size_t)row * K + k0 + c4 * 4;
            uint32_t dst = (uint32_t)__cvta_generic_to_shared(&As[buf][row * STR + c4 * 4]);
            asm volatile("cp.async.cg.shared.global [%0], [%1], 16;\n" :: "r"(dst), "l"(src) : "memory");
        }
#pragma unroll
        for (int i = 0; i < 2; ++i) {
            int idx = tid + i * 256;
            int row = idx >> 2, c4 = idx & 3;
            const float* src = Bg + (size_t)row * K + k0 + c4 * 4;
            uint32_t dst = (uint32_t)__cvta_generic_to_shared(&Bs[buf][row * STR + c4 * 4]);
            asm volatile("cp.async.cg.shared.global [%0], [%1], 16;\n" :: "r"(dst), "l"(src) : "memory");
        }
        asm volatile("cp.async.commit_group;\n" ::: "memory");
    };

    load_tile(0, 0);

    for (int kc = 0; kc < nk; ++kc) {
        asm volatile("cp.async.wait_group 0;\n" ::: "memory");
        __syncthreads();
        if (kc + 1 < nk) load_tile((kc + 1) & 1, kc + 1);
        const int buf = kc & 1;

#pragma unroll
        for (int kk = 0; kk < BKK; kk += 8) {
            uint32_t a[4][4], b[4][2];
#pragma unroll
            for (int mi = 0; mi < 4; ++mi) {
                int r = wm + mi * 16 + g;
                a[mi][0] = f2tf32(As[buf][(r    ) * STR + kk + tg    ]);
                a[mi][1] = f2tf32(As[buf][(r + 8) * STR + kk + tg    ]);
                a[mi][2] = f2tf32(As[buf][(r    ) * STR + kk + tg + 4]);
                a[mi][3] = f2tf32(As[buf][(r + 8) * STR + kk + tg + 4]);
            }
#pragma unroll
            for (int ni = 0; ni < 4; ++ni) {
                int r = wn + ni * 8 + g;
                b[ni][0] = f2tf32(Bs[buf][r * STR + kk + tg    ]);
                b[ni][1] = f2tf32(Bs[buf][r * STR + kk + tg + 4]);
            }
#pragma unroll
            for (int mi = 0; mi < 4; ++mi)
#pragma unroll
                for (int ni = 0; ni < 4; ++ni)
                    asm volatile(
                        "mma.sync.aligned.m16n8k8.row.col.f32.tf32.tf32.f32 "
                        "{%0,%1,%2,%3}, {%4,%5,%6,%7}, {%8,%9}, {%0,%1,%2,%3};"
                        : "+f"(c[mi][ni][0]), "+f"(c[mi][ni][1]),
                          "+f"(c[mi][ni][2]), "+f"(c[mi][ni][3])
                        : "r"(a[mi][0]), "r"(a[mi][1]), "r"(a[mi][2]), "r"(a[mi][3]),
                          "r"(b[ni][0]), "r"(b[ni][1]));
        }
        __syncthreads();
    }

    // epilogue
#pragma unroll
    for (int mi = 0; mi < 4; ++mi) {
        int m0 = blockIdx.y * BM + wm + mi * 16 + g;
#pragma unroll
        for (int ni = 0; ni < 4; ++ni) {
            int n0 = blockIdx.x * BN + wn + ni * 8 + 2 * tg;
            float* p0 = C + (size_t)m0 * N + n0;
            float* p1 = C + (size_t)(m0 + 8) * N + n0;
            if (accumulate) {
                p0[0] += c[mi][ni][0]; p0[1] += c[mi][ni][1];
                p1[0] += c[mi][ni][2]; p1[1] += c[mi][ni][3];
            } else {
                p0[0] = c[mi][ni][0]; p0[1] = c[mi][ni][1];
                p1[0] = c[mi][ni][2]; p1[1] = c[mi][ni][3];
            }
        }
    }
}

// ---------------------------------------------------------------------------
// Fused causal depthwise conv (k=4, pad left 3) + bias + silu(x)*silu(z)*comb.
// zx layout: [token][0..DI) = z, [DI..2DI) = x. Output xact [token][DI].
// Early-out when this expert isn't selected for the token (comb == 0).
// ---------------------------------------------------------------------------
__global__ void conv_act_kernel(const float* __restrict__ zx,
                                const float* __restrict__ cw,   // [DI][4] this expert
                                const float* __restrict__ cb,   // [DI]
                                int e,
                                float* __restrict__ xact)
{
    int idx = blockIdx.x * blockDim.x + threadIdx.x;   // over NT * DI/4
    const int c4 = idx & (DI / 4 - 1);
    const int t  = idx >> 9;                            // DI/4 = 512
    if (t >= NT) return;

    float4* outp = reinterpret_cast<float4*>(xact + (size_t)t * DI + c4 * 4);
    const float cwt = g_comb[(size_t)t * NE + e];
    if (cwt == 0.f) { *outp = make_float4(0.f, 0.f, 0.f, 0.f); return; }

    const int b = t / Ss, s = t & (Ss - 1);
    const int c = c4 * 4;

    const float4* cwf = reinterpret_cast<const float4*>(cw);
    float4 w0 = cwf[c4 * 4 + 0];   // taps of channel c
    float4 w1 = cwf[c4 * 4 + 1];   // taps of channel c+1
    float4 w2 = cwf[c4 * 4 + 2];
    float4 w3 = cwf[c4 * 4 + 3];
    float4 acc = reinterpret_cast<const float4*>(cb)[c4];

#pragma unroll
    for (int j = 0; j < 4; ++j) {
        int sj = s - 3 + j;
        if (sj < 0) continue;
        const float4 xv = *reinterpret_cast<const float4*>(
            zx + (size_t)(b * Ss + sj) * (2 * DI) + DI + c);
        float t0 = (j == 0) ? w0.x : (j == 1) ? w0.y : (j == 2) ? w0.z : w0.w;
        float t1 = (j == 0) ? w1.x : (j == 1) ? w1.y : (j == 2) ? w1.z : w1.w;
        float t2 = (j == 0) ? w2.x : (j == 1) ? w2.y : (j == 2) ? w2.z : w2.w;
        float t3 = (j == 0) ? w3.x : (j == 1) ? w3.y : (j == 2) ? w3.z : w3.w;
        acc.x += t0 * xv.x; acc.y += t1 * xv.y;
        acc.z += t2 * xv.z; acc.w += t3 * xv.w;
    }

    const float4 z = *reinterpret_cast<const float4*>(zx + (size_t)t * (2 * DI) + c);
    float4 o;
    o.x = silu_(acc.x) * silu_(z.x) * cwt;
    o.y = silu_(acc.y) * silu_(z.y) * cwt;
    o.z = silu_(acc.z) * silu_(z.z) * cwt;
    o.w = silu_(acc.w) * silu_(z.w) * cwt;
    *outp = o;
}

// ---------------------------------------------------------------------------
extern "C" void kernel_launch(void* const* d_in, const int* in_sizes, int n_in,
                              void* d_out, int out_size)
{
    const float* h   = (const float*)d_in[0];   // [B,S,D]
    const float* inw = (const float*)d_in[1];   // [E, 2*DI, D]
    const float* cw  = (const float*)d_in[2];   // [E, DI, 1, 4]
    const float* cb  = (const float*)d_in[3];   // [E, DI]
    const float* ow  = (const float*)d_in[4];   // [E, D, DI]
    const float* rw1 = (const float*)d_in[5];   // [128, D]
    const float* rw2 = (const float*)d_in[6];   // [E, 128]
    float* out = (float*)d_out;                 // [B,S,D]

    void *zxp = nullptr, *xap = nullptr;
    cudaGetSymbolAddress(&zxp, g_zx);
    cudaGetSymbolAddress(&xap, g_xact);
    float* zx = (float*)zxp;
    float* xa = (float*)xap;

    router_kernel<<<NT, 128>>>(h, rw1, rw2);
    cudaMemsetAsync(out, 0, (size_t)NT * Dd * sizeof(float));

    dim3 g1((2 * DI) / BN, NT / BM);   // in_proj: 32 x 64
    dim3 g2(Dd / BN, NT / BM);         // out_proj: 8 x 64
    const int conv_blocks = (NT * (DI / 4)) / 256;

    for (int e = 0; e < NE; ++e) {
        gemm_tn<<<g1, 256>>>(h, inw + (size_t)e * 2 * DI * Dd, zx, NT, 2 * DI, Dd, 0);
        conv_act_kernel<<<conv_blocks, 256>>>(zx, cw + (size_t)e * DI * 4,
                                              cb + (size_t)e * DI, e, xa);
        gemm_tn<<<g2, 256>>>(xa, ow + (size_t)e * Dd * DI, out, NT, Dd, DI, 1);
    }
}

// round 3
// speedup vs baseline: 2.1355x; 2.1355x over previous
#include <cuda_runtime.h>
#include <cstdint>
#include <cstddef>

// Problem constants
#define Bb 4
#define Ss 2048
#define Dd 1024
#define DI 2048          // D_INNER
#define NT (Bb*Ss)       // 8192 tokens
#define NE 8
#define RHID 128

// GEMM tile config
#define BM 128
#define BN 128
#define BKK 16
#define STR 20           // padded smem row stride (floats)

// Scratch (device globals: allocation-free rule)
__device__ float g_zbuf[(size_t)NT * DI];     // z at selected tokens (list order)
__device__ float g_xbuf[(size_t)NT * DI];     // x (conv input) at needed tokens
__device__ float g_xact[(size_t)NT * DI];     // gated activation * comb (list order)
__device__ float g_rh[(size_t)NT * RHID];     // silu(router hidden), fp32-exact
__device__ float g_comb[(size_t)NT * NE];     // routing combine weights
__device__ int   g_selflag[(size_t)NT * NE];  // 1 if token selects expert
__device__ int   g_sel_idx[NE * NT];          // tokens selecting expert e
__device__ int   g_x_idx[NE * NT];            // tokens needed for conv input
__device__ int   g_posx[NE * NT];             // token -> position in x list
__device__ int   g_cnts[2 * NE];              // [0..7]=sel counts, [8..15]=x counts

__device__ __forceinline__ float silu_(float x) { return x / (1.0f + expf(-x)); }

__device__ __forceinline__ uint32_t f2tf32(float f) {
    uint32_t u;
    asm("cvt.rna.tf32.f32 %0, %1;" : "=r"(u) : "f"(f));
    return u;
}

// ---------------------------------------------------------------------------
// Router layer 1, FULL FP32: rh = silu(h @ W1^T).  [NT,1024] x [128,1024]^T.
// Block: 64 tokens x 128 hidden, 256 threads, K-chunks of 32.
// Routing decisions are precision-critical: no TF32 here.
// ---------------------------------------------------------------------------
__global__ __launch_bounds__(256) void router_l1(const float* __restrict__ h,
                                                 const float* __restrict__ w1,
                                                 float* __restrict__ rh)
{
    __shared__ float As[64][33];
    __shared__ float Ws[128][33];

    const int tid = threadIdx.x;
    const int t0 = blockIdx.x * 64;
    const int ty = tid >> 4;        // 0..15 -> token group (4 tokens)
    const int tx = tid & 15;        // 0..15 -> hidden group (8 hidden)

    float acc[4][8];
#pragma unroll
    for (int i = 0; i < 4; ++i)
#pragma unroll
        for (int j = 0; j < 8; ++j) acc[i][j] = 0.f;

    const int arow = tid >> 2, acol = (tid & 3) * 8;    // A: 64x32, 8 floats/thr
    const int wrow = tid >> 1, wcol = (tid & 1) * 16;   // W: 128x32, 16 floats/thr

    for (int k0 = 0; k0 < Dd; k0 += 32) {
        float4 a0 = *(const float4*)&h[(size_t)(t0 + arow) * Dd + k0 + acol];
        float4 a1 = *(const float4*)&h[(size_t)(t0 + arow) * Dd + k0 + acol + 4];
        As[arow][acol + 0] = a0.x; As[arow][acol + 1] = a0.y;
        As[arow][acol + 2] = a0.z; As[arow][acol + 3] = a0.w;
        As[arow][acol + 4] = a1.x; As[arow][acol + 5] = a1.y;
        As[arow][acol + 6] = a1.z; As[arow][acol + 7] = a1.w;
#pragma unroll
        for (int q = 0; q < 4; ++q) {
            float4 w = *(const float4*)&w1[(size_t)wrow * Dd + k0 + wcol + q * 4];
            Ws[wrow][wcol + q * 4 + 0] = w.x; Ws[wrow][wcol + q * 4 + 1] = w.y;
            Ws[wrow][wcol + q * 4 + 2] = w.z; Ws[wrow][wcol + q * 4 + 3] = w.w;
        }
        __syncthreads();

#pragma unroll 8
        for (int k = 0; k < 32; ++k) {
            float a[4], b[8];
#pragma unroll
            for (int i = 0; i < 4; ++i) a[i] = As[ty * 4 + i][k];
#pragma unroll
            for (int j = 0; j < 8; ++j) b[j] = Ws[tx * 8 + j][k];
#pragma unroll
            for (int i = 0; i < 4; ++i)
#pragma unroll
                for (int j = 0; j < 8; ++j) acc[i][j] += a[i] * b[j];
        }
        __syncthreads();
    }

#pragma unroll
    for (int i = 0; i < 4; ++i) {
        int t = t0 + ty * 4 + i;
#pragma unroll
        for (int j = 0; j < 8; ++j)
            rh[(size_t)t * RHID + tx * 8 + j] = silu_(acc[i][j]);
    }
}

// ---------------------------------------------------------------------------
// Router finish (fp32): logits = rh @ W2^T, top-2 softmax, comb + lists.
// One warp per token.
// ---------------------------------------------------------------------------
__global__ void router_finish(const float* __restrict__ rh,
                              const float* __restrict__ w2)
{
    int t = (blockIdx.x * blockDim.x + threadIdx.x) >> 5;
    int lane = threadIdx.x & 31;
    if (t >= NT) return;

    const float* r = rh + (size_t)t * RHID;
    float v0 = r[lane], v1 = r[lane + 32], v2 = r[lane + 64], v3 = r[lane + 96];

    float lg[NE];
#pragma unroll
    for (int e = 0; e < NE; ++e) {
        const float* w = w2 + e * RHID;
        float p = v0 * w[lane] + v1 * w[lane + 32] + v2 * w[lane + 64] + v3 * w[lane + 96];
#pragma unroll
        for (int o = 16; o; o >>= 1) p += __shfl_xor_sync(0xffffffffu, p, o);
        lg[e] = p;
    }

    if (lane == 0) {
        int i1 = 0; float l1 = lg[0];
#pragma unroll
        for (int e = 1; e < NE; ++e) if (lg[e] > l1) { l1 = lg[e]; i1 = e; }
        int i2 = -1; float l2 = -1e30f;
#pragma unroll
        for (int e = 0; e < NE; ++e) { if (e == i1) continue; if (lg[e] > l2) { l2 = lg[e]; i2 = e; } }
        float wtop = 1.f / (1.f + expf(l2 - l1));
        float* cb = &g_comb[(size_t)t * NE];
        int* sf = &g_selflag[(size_t)t * NE];
#pragma unroll
        for (int e = 0; e < NE; ++e) { cb[e] = 0.f; sf[e] = 0; }
        cb[i1] = wtop;       sf[i1] = 1;
        cb[i2] = 1.f - wtop; sf[i2] = 1;
        int q1 = atomicAdd(&g_cnts[i1], 1); g_sel_idx[i1 * NT + q1] = t;
        int q2 = atomicAdd(&g_cnts[i2], 1); g_sel_idx[i2 * NT + q2] = t;
    }
}

// ---------------------------------------------------------------------------
// Build conv-input (dilated) token lists: token t needed for expert e if any
// of tokens t..t+3 (same batch) SELECTS e (flag-based, not weight!=0).
// ---------------------------------------------------------------------------
__global__ void build_xlists()
{
    int t = blockIdx.x * blockDim.x + threadIdx.x;
    int e = blockIdx.y;
    if (t >= NT) return;
    int b = t >> 11, s = t & (Ss - 1);
    bool need = false;
#pragma unroll
    for (int j = 0; j < 4; ++j) {
        int sj = s + j;
        if (sj < Ss) need |= (g_selflag[(size_t)(b * Ss + sj) * NE + e] != 0);
    }
    if (need) {
        int p = atomicAdd(&g_cnts[NE + e], 1);
        g_x_idx[e * NT + p] = t;
        g_posx[e * NT + t] = p;
    }
}

// ---------------------------------------------------------------------------
// TF32 GEMM (TN): C[M,N] op= A[M,K] * W[N,K]^T.
// Runtime M (Mptr), optional A-row gather (a_idx), C-row scatter (c_idx).
// mode: 0 = store, 1 = accumulate.
// 128x128x16 tiles, double-buffered cp.async, 8 warps, 64x32/warp.
// ---------------------------------------------------------------------------
__global__ __launch_bounds__(256, 2) void gemm_tn_v2(
    const float* __restrict__ A, const float* __restrict__ W, float* __restrict__ C,
    const int* __restrict__ Mptr, int Mfix, int N, int K,
    const int* __restrict__ a_idx, const int* __restrict__ c_idx, int mode)
{
    const int M = Mptr ? *Mptr : Mfix;
    if ((int)blockIdx.y * BM >= M) return;

    __shared__ float As[2][BM * STR];
    __shared__ float Bs[2][BN * STR];

    const int tid  = threadIdx.x;
    const int lane = tid & 31;
    const int warp = tid >> 5;
    const int g  = lane >> 2;
    const int tg = lane & 3;
    const int wm = (warp & 1) * 64;
    const int wn = (warp >> 1) * 32;

    const int r0   = tid >> 2;
    const int roff = (tid & 3) * 4;
    const int i0 = blockIdx.y * BM + r0;
    const int i1 = i0 + 64;
    const int ic0 = min(i0, M - 1);
    const int ic1 = min(i1, M - 1);
    const float* arow0 = A + (size_t)(a_idx ? a_idx[ic0] : ic0) * K + roff;
    const float* arow1 = A + (size_t)(a_idx ? a_idx[ic1] : ic1) * K + roff;
    const float* Bg = W + (size_t)(blockIdx.x * BN) * K;
    const float* brow0 = Bg + (size_t)r0 * K + roff;
    const float* brow1 = Bg + (size_t)(r0 + 64) * K + roff;

    const uint32_t sa0 = (uint32_t)__cvta_generic_to_shared(&As[0][r0 * STR + roff]);
    const uint32_t sa1 = (uint32_t)__cvta_generic_to_shared(&As[0][(r0 + 64) * STR + roff]);
    const uint32_t sb0 = (uint32_t)__cvta_generic_to_shared(&Bs[0][r0 * STR + roff]);
    const uint32_t sb1 = (uint32_t)__cvta_generic_to_shared(&Bs[0][(r0 + 64) * STR + roff]);
    const uint32_t bufstep = (uint32_t)(BM * STR * sizeof(float));

    float c[4][4][4];
#pragma unroll
    for (int i = 0; i < 4; ++i)
#pragma unroll
        for (int j = 0; j < 4; ++j)
#pragma unroll
            for (int r = 0; r < 4; ++r) c[i][j][r] = 0.f;

    const int nk = K / BKK;

    auto load_tile = [&](int buf, int kc) {
        const int k0 = kc * BKK;
        const uint32_t bo = buf * bufstep;
        asm volatile("cp.async.cg.shared.global [%0], [%1], 16;\n" :: "r"(sa0 + bo), "l"(arow0 + k0) : "memory");
        asm volatile("cp.async.cg.shared.global [%0], [%1], 16;\n" :: "r"(sa1 + bo), "l"(arow1 + k0) : "memory");
        asm volatile("cp.async.cg.shared.global [%0], [%1], 16;\n" :: "r"(sb0 + bo), "l"(brow0 + k0) : "memory");
        asm volatile("cp.async.cg.shared.global [%0], [%1], 16;\n" :: "r"(sb1 + bo), "l"(brow1 + k0) : "memory");
        asm volatile("cp.async.commit_group;\n" ::: "memory");
    };

    load_tile(0, 0);

    for (int kc = 0; kc < nk; ++kc) {
        asm volatile("cp.async.wait_group 0;\n" ::: "memory");
        __syncthreads();
        if (kc + 1 < nk) load_tile((kc + 1) & 1, kc + 1);
        const int buf = kc & 1;

#pragma unroll
        for (int kk = 0; kk < BKK; kk += 8) {
            uint32_t a[4][4], b[4][2];
#pragma unroll
            for (int mi = 0; mi < 4; ++mi) {
                int r = wm + mi * 16 + g;
                a[mi][0] = f2tf32(As[buf][(r    ) * STR + kk + tg    ]);
                a[mi][1] = f2tf32(As[buf][(r + 8) * STR + kk + tg    ]);
                a[mi][2] = f2tf32(As[buf][(r    ) * STR + kk + tg + 4]);
                a[mi][3] = f2tf32(As[buf][(r + 8) * STR + kk + tg + 4]);
            }
#pragma unroll
            for (int ni = 0; ni < 4; ++ni) {
                int r = wn + ni * 8 + g;
                b[ni][0] = f2tf32(Bs[buf][r * STR + kk + tg    ]);
                b[ni][1] = f2tf32(Bs[buf][r * STR + kk + tg + 4]);
            }
#pragma unroll
            for (int mi = 0; mi < 4; ++mi)
#pragma unroll
                for (int ni = 0; ni < 4; ++ni)
                    asm volatile(
                        "mma.sync.aligned.m16n8k8.row.col.f32.tf32.tf32.f32 "
                        "{%0,%1,%2,%3}, {%4,%5,%6,%7}, {%8,%9}, {%0,%1,%2,%3};"
                        : "+f"(c[mi][ni][0]), "+f"(c[mi][ni][1]),
                          "+f"(c[mi][ni][2]), "+f"(c[mi][ni][3])
                        : "r"(a[mi][0]), "r"(a[mi][1]), "r"(a[mi][2]), "r"(a[mi][3]),
                          "r"(b[ni][0]), "r"(b[ni][1]));
        }
        __syncthreads();
    }

#pragma unroll
    for (int mi = 0; mi < 4; ++mi) {
        int m0 = blockIdx.y * BM + wm + mi * 16 + g;
        int m1 = m0 + 8;
#pragma unroll
        for (int ni = 0; ni < 4; ++ni) {
            int n0 = blockIdx.x * BN + wn + ni * 8 + 2 * tg;
            float v0 = c[mi][ni][0], v1 = c[mi][ni][1];
            float v2 = c[mi][ni][2], v3 = c[mi][ni][3];
            if (m0 < M) {
                int row = c_idx ? c_idx[m0] : m0;
                float* p = C + (size_t)row * N + n0;
                if (mode == 1) { p[0] += v0; p[1] += v1; } else { p[0] = v0; p[1] = v1; }
            }
            if (m1 < M) {
                int row = c_idx ? c_idx[m1] : m1;
                float* p = C + (size_t)row * N + n0;
                if (mode == 1) { p[0] += v2; p[1] += v3; } else { p[0] = v2; p[1] = v3; }
            }
        }
    }
}

// ---------------------------------------------------------------------------
// Sparse fused conv(k=4, causal) + bias + silu(x)*silu(z)*comb.
// ---------------------------------------------------------------------------
__global__ void conv_act_sparse(const float* __restrict__ cw,   // [DI][4], expert e
                                const float* __restrict__ cb,   // [DI]
                                int e)
{
    const int cnt = g_cnts[e];
    const int total = cnt * (DI / 4);
    const int* sel = g_sel_idx + e * NT;
    const int* posx = g_posx + e * NT;
    const float4* cwf = reinterpret_cast<const float4*>(cw);
    const float4* cbf = reinterpret_cast<const float4*>(cb);

    for (int idx = blockIdx.x * blockDim.x + threadIdx.x; idx < total;
         idx += gridDim.x * blockDim.x) {
        const int i  = idx >> 9;           // DI/4 = 512
        const int c4 = idx & 511;
        const int c  = c4 * 4;
        const int t  = sel[i];
        const float wgt = g_comb[(size_t)t * NE + e];
        const int b = t >> 11, s = t & (Ss - 1);

        float4 w0 = cwf[c4 * 4 + 0];
        float4 w1 = cwf[c4 * 4 + 1];
        float4 w2 = cwf[c4 * 4 + 2];
        float4 w3 = cwf[c4 * 4 + 3];
        float4 acc = cbf[c4];

#pragma unroll
        for (int j = 0; j < 4; ++j) {
            int sj = s - 3 + j;
            if (sj < 0) continue;
            int r = posx[b * Ss + sj];
            const float4 xv = *reinterpret_cast<const float4*>(g_xbuf + (size_t)r * DI + c);
            float t0 = (j == 0) ? w0.x : (j == 1) ? w0.y : (j == 2) ? w0.z : w0.w;
            float t1 = (j == 0) ? w1.x : (j == 1) ? w1.y : (j == 2) ? w1.z : w1.w;
            float t2 = (j == 0) ? w2.x : (j == 1) ? w2.y : (j == 2) ? w2.z : w2.w;
            float t3 = (j == 0) ? w3.x : (j == 1) ? w3.y : (j == 2) ? w3.z : w3.w;
            acc.x += t0 * xv.x; acc.y += t1 * xv.y;
            acc.z += t2 * xv.z; acc.w += t3 * xv.w;
        }

        const float4 z = *reinterpret_cast<const float4*>(g_zbuf + (size_t)i * DI + c);
        float4 o;
        o.x = silu_(acc.x) * silu_(z.x) * wgt;
        o.y = silu_(acc.y) * silu_(z.y) * wgt;
        o.z = silu_(acc.z) * silu_(z.z) * wgt;
        o.w = silu_(acc.w) * silu_(z.w) * wgt;
        *reinterpret_cast<float4*>(g_xact + (size_t)i * DI + c) = o;
    }
}

// ---------------------------------------------------------------------------
extern "C" void kernel_launch(void* const* d_in, const int* in_sizes, int n_in,
                              void* d_out, int out_size)
{
    const float* h   = (const float*)d_in[0];   // [B,S,D]
    const float* inw = (const float*)d_in[1];   // [E, 2*DI, D]
    const float* cw  = (const float*)d_in[2];   // [E, DI, 1, 4]
    const float* cb  = (const float*)d_in[3];   // [E, DI]
    const float* ow  = (const float*)d_in[4];   // [E, D, DI]
    const float* rw1 = (const float*)d_in[5];   // [128, D]
    const float* rw2 = (const float*)d_in[6];   // [E, 128]
    float* out = (float*)d_out;                 // [B,S,D]

    void *zb, *xb, *xa, *rhp, *cntp, *selp, *xip;
    cudaGetSymbolAddress(&zb, g_zbuf);
    cudaGetSymbolAddress(&xb, g_xbuf);
    cudaGetSymbolAddress(&xa, g_xact);
    cudaGetSymbolAddress(&rhp, g_rh);
    cudaGetSymbolAddress(&cntp, g_cnts);
    cudaGetSymbolAddress(&selp, g_sel_idx);
    cudaGetSymbolAddress(&xip, g_x_idx);
    float* zbuf = (float*)zb;
    float* xbuf = (float*)xb;
    float* xact = (float*)xa;
    float* rh   = (float*)rhp;
    int* cnts   = (int*)cntp;
    int* selidx = (int*)selp;
    int* xidx   = (int*)xip;

    cudaMemsetAsync(cnts, 0, 2 * NE * sizeof(int));
    cudaMemsetAsync(out, 0, (size_t)NT * Dd * sizeof(float));

    // router, all fp32
    router_l1<<<NT / 64, 256>>>(h, rw1, rh);
    router_finish<<<(NT * 32) / 256, 256>>>(rh, rw2);
    build_xlists<<<dim3(NT / 256, NE), 256>>>();

    const dim3 gin(DI / BN, NT / BM);     // 16 x 64 (early-exit past M)
    const dim3 gout(Dd / BN, NT / BM);    // 8 x 64

    for (int e = 0; e < NE; ++e) {
        const int* selE = selidx + e * NT;
        const int* xE   = xidx + e * NT;
        const int* cntS = cnts + e;
        const int* cntX = cnts + NE + e;
        const float* wz = inw + (size_t)e * 2 * DI * Dd;           // z rows [0,DI)
        const float* wx = wz + (size_t)DI * Dd;                    // x rows [DI,2DI)

        // z at selected tokens -> zbuf (list order)
        gemm_tn_v2<<<gin, 256>>>(h, wz, zbuf, cntS, 0, DI, Dd, selE, nullptr, 0);
        // x (conv input) at dilated token set -> xbuf (list order)
        gemm_tn_v2<<<gin, 256>>>(h, wx, xbuf, cntX, 0, DI, Dd, xE, nullptr, 0);
        // fused conv + gate + combine weight
        conv_act_sparse<<<1024, 256>>>(cw + (size_t)e * DI * 4, cb + (size_t)e * DI, e);
        // out_proj, scatter-accumulate into output rows
        gemm_tn_v2<<<gout, 256>>>(xact, ow + (size_t)e * Dd * DI, out, cntS, 0,
                                  Dd, DI, nullptr, selE, 1);
    }
}

// round 4
// speedup vs baseline: 3.1132x; 1.4578x over previous
#include <cuda_runtime.h>
#include <cstdint>
#include <cstddef>

// Problem constants
#define Bb 4
#define Ss 2048
#define Dd 1024
#define DI 2048          // D_INNER
#define NT (Bb*Ss)       // 8192 tokens
#define NE 8
#define RHID 128

// GEMM tile config
#define BM 128
#define BN 128
#define BKK 16
#define STR 20           // padded smem row stride (floats)

// Scratch (device globals: allocation-free rule)
__device__ float g_zx[(size_t)16 * NT * DI];    // job j (=2e:z, 2e+1:x) output
__device__ float g_xact[(size_t)NE * NT * DI];  // gated act * comb (tf32-rounded)
__device__ float g_outbuf[(size_t)NE * NT * Dd];// per-expert out_proj (list order)
__device__ float g_hr[(size_t)NT * Dd];         // tf32-rounded h
__device__ float g_inwr[(size_t)NE * 2 * DI * Dd]; // tf32-rounded in_proj_w
__device__ float g_owr[(size_t)NE * Dd * DI];   // tf32-rounded out_proj_w
__device__ float g_rh[(size_t)NT * RHID];       // silu(router hidden), fp32
__device__ float g_comb[(size_t)NT * NE];
__device__ int   g_selflag[(size_t)NT * NE];
__device__ int   g_lists[16 * NT];              // job j token list at j*NT
__device__ int   g_posx[NE * NT];               // token -> pos in x list
__device__ int4  g_tokmap[NT];                  // (e1,q1,e2,q2)
__device__ int   g_cnts2[16];                   // count per job

__device__ __forceinline__ float silu_(float x) { return x / (1.0f + expf(-x)); }

__device__ __forceinline__ float round_tf32f(float f) {
    uint32_t u;
    asm("cvt.rna.tf32.f32 %0, %1;" : "=r"(u) : "f"(f));
    return __uint_as_float(u);
}

// ---------------------------------------------------------------------------
// Elementwise tf32 rounding pass (vectorized, grid-stride).
// ---------------------------------------------------------------------------
__global__ void round_pass(const float4* __restrict__ src, float4* __restrict__ dst,
                           int n4)
{
    for (int i = blockIdx.x * blockDim.x + threadIdx.x; i < n4;
         i += gridDim.x * blockDim.x) {
        float4 v = src[i];
        v.x = round_tf32f(v.x); v.y = round_tf32f(v.y);
        v.z = round_tf32f(v.z); v.w = round_tf32f(v.w);
        dst[i] = v;
    }
}

// ---------------------------------------------------------------------------
// Router layer 1, FULL FP32: rh = silu(h @ W1^T).
// ---------------------------------------------------------------------------
__global__ __launch_bounds__(256) void router_l1(const float* __restrict__ h,
                                                 const float* __restrict__ w1,
                                                 float* __restrict__ rh)
{
    __shared__ float As[64][33];
    __shared__ float Ws[128][33];

    const int tid = threadIdx.x;
    const int t0 = blockIdx.x * 64;
    const int ty = tid >> 4;
    const int tx = tid & 15;

    float acc[4][8];
#pragma unroll
    for (int i = 0; i < 4; ++i)
#pragma unroll
        for (int j = 0; j < 8; ++j) acc[i][j] = 0.f;

    const int arow = tid >> 2, acol = (tid & 3) * 8;
    const int wrow = tid >> 1, wcol = (tid & 1) * 16;

    for (int k0 = 0; k0 < Dd; k0 += 32) {
        float4 a0 = *(const float4*)&h[(size_t)(t0 + arow) * Dd + k0 + acol];
        float4 a1 = *(const float4*)&h[(size_t)(t0 + arow) * Dd + k0 + acol + 4];
        As[arow][acol + 0] = a0.x; As[arow][acol + 1] = a0.y;
        As[arow][acol + 2] = a0.z; As[arow][acol + 3] = a0.w;
        As[arow][acol + 4] = a1.x; As[arow][acol + 5] = a1.y;
        As[arow][acol + 6] = a1.z; As[arow][acol + 7] = a1.w;
#pragma unroll
        for (int q = 0; q < 4; ++q) {
            float4 w = *(const float4*)&w1[(size_t)wrow * Dd + k0 + wcol + q * 4];
            Ws[wrow][wcol + q * 4 + 0] = w.x; Ws[wrow][wcol + q * 4 + 1] = w.y;
            Ws[wrow][wcol + q * 4 + 2] = w.z; Ws[wrow][wcol + q * 4 + 3] = w.w;
        }
        __syncthreads();

#pragma unroll 8
        for (int k = 0; k < 32; ++k) {
            float a[4], b[8];
#pragma unroll
            for (int i = 0; i < 4; ++i) a[i] = As[ty * 4 + i][k];
#pragma unroll
            for (int j = 0; j < 8; ++j) b[j] = Ws[tx * 8 + j][k];
#pragma unroll
            for (int i = 0; i < 4; ++i)
#pragma unroll
                for (int j = 0; j < 8; ++j) acc[i][j] += a[i] * b[j];
        }
        __syncthreads();
    }

#pragma unroll
    for (int i = 0; i < 4; ++i) {
        int t = t0 + ty * 4 + i;
#pragma unroll
        for (int j = 0; j < 8; ++j)
            rh[(size_t)t * RHID + tx * 8 + j] = silu_(acc[i][j]);
    }
}

// ---------------------------------------------------------------------------
// Router finish (fp32): logits, top-2 softmax, comb/selflag/lists/tokmap.
// ---------------------------------------------------------------------------
__global__ void router_finish(const float* __restrict__ rh,
                              const float* __restrict__ w2)
{
    int t = (blockIdx.x * blockDim.x + threadIdx.x) >> 5;
    int lane = threadIdx.x & 31;
    if (t >= NT) return;

    const float* r = rh + (size_t)t * RHID;
    float v0 = r[lane], v1 = r[lane + 32], v2 = r[lane + 64], v3 = r[lane + 96];

    float lg[NE];
#pragma unroll
    for (int e = 0; e < NE; ++e) {
        const float* w = w2 + e * RHID;
        float p = v0 * w[lane] + v1 * w[lane + 32] + v2 * w[lane + 64] + v3 * w[lane + 96];
#pragma unroll
        for (int o = 16; o; o >>= 1) p += __shfl_xor_sync(0xffffffffu, p, o);
        lg[e] = p;
    }

    if (lane == 0) {
        int i1 = 0; float l1 = lg[0];
#pragma unroll
        for (int e = 1; e < NE; ++e) if (lg[e] > l1) { l1 = lg[e]; i1 = e; }
        int i2 = -1; float l2 = -1e30f;
#pragma unroll
        for (int e = 0; e < NE; ++e) { if (e == i1) continue; if (lg[e] > l2) { l2 = lg[e]; i2 = e; } }
        float wtop = 1.f / (1.f + expf(l2 - l1));
        float* cb = &g_comb[(size_t)t * NE];
        int* sf = &g_selflag[(size_t)t * NE];
#pragma unroll
        for (int e = 0; e < NE; ++e) { cb[e] = 0.f; sf[e] = 0; }
        cb[i1] = wtop;       sf[i1] = 1;
        cb[i2] = 1.f - wtop; sf[i2] = 1;
        int q1 = atomicAdd(&g_cnts2[2 * i1], 1); g_lists[(2 * i1) * NT + q1] = t;
        int q2 = atomicAdd(&g_cnts2[2 * i2], 1); g_lists[(2 * i2) * NT + q2] = t;
        g_tokmap[t] = make_int4(i1, q1, i2, q2);
    }
}

// ---------------------------------------------------------------------------
// Conv-input (dilated) token lists.
// ---------------------------------------------------------------------------
__global__ void build_xlists()
{
    int t = blockIdx.x * blockDim.x + threadIdx.x;
    int e = blockIdx.y;
    if (t >= NT) return;
    int b = t >> 11, s = t & (Ss - 1);
    bool need = false;
#pragma unroll
    for (int j = 0; j < 4; ++j) {
        int sj = s + j;
        if (sj < Ss) need |= (g_selflag[(size_t)(b * Ss + sj) * NE + e] != 0);
    }
    if (need) {
        int p = atomicAdd(&g_cnts2[2 * e + 1], 1);
        g_lists[(2 * e + 1) * NT + p] = t;
        g_posx[e * NT + t] = p;
    }
}

// ---------------------------------------------------------------------------
// TF32 GEMM (TN), batched over blockIdx.z: C[M,N] = A[M,K] * W[N,K]^T.
// Inputs already tf32-rounded -> NO cvt in the mainloop.
// M = cnts[mBase + z*mStride] (early-exit). Optional A-row gather per z.
// ---------------------------------------------------------------------------
__global__ __launch_bounds__(256, 2) void gemm_tn_v3(
    const float* __restrict__ A, const float* __restrict__ W, float* __restrict__ C,
    const int* __restrict__ cnts, int mBase, int mStride,
    int N, int K,
    size_t aStrideZ, size_t wStrideZ, size_t cStrideZ,
    const int* __restrict__ idx, size_t idxStrideZ)
{
    const int z = blockIdx.z;
    const int M = cnts[mBase + z * mStride];
    if ((int)blockIdx.y * BM >= M) return;

    A += (size_t)z * aStrideZ;
    W += (size_t)z * wStrideZ;
    C += (size_t)z * cStrideZ;
    const int* aidx = idx ? idx + (size_t)z * idxStrideZ : nullptr;

    __shared__ float As[2][BM * STR];
    __shared__ float Bs[2][BN * STR];

    const int tid  = threadIdx.x;
    const int lane = tid & 31;
    const int warp = tid >> 5;
    const int g  = lane >> 2;
    const int tg = lane & 3;
    const int wm = (warp & 1) * 64;
    const int wn = (warp >> 1) * 32;

    const int r0   = tid >> 2;
    const int roff = (tid & 3) * 4;
    const int i0 = blockIdx.y * BM + r0;
    const int i1 = i0 + 64;
    const int ic0 = min(i0, M - 1);
    const int ic1 = min(i1, M - 1);
    const float* arow0 = A + (size_t)(aidx ? aidx[ic0] : ic0) * K + roff;
    const float* arow1 = A + (size_t)(aidx ? aidx[ic1] : ic1) * K + roff;
    const float* Bg = W + (size_t)(blockIdx.x * BN) * K;
    const float* brow0 = Bg + (size_t)r0 * K + roff;
    const float* brow1 = Bg + (size_t)(r0 + 64) * K + roff;

    const uint32_t sa0 = (uint32_t)__cvta_generic_to_shared(&As[0][r0 * STR + roff]);
    const uint32_t sa1 = (uint32_t)__cvta_generic_to_shared(&As[0][(r0 + 64) * STR + roff]);
    const uint32_t sb0 = (uint32_t)__cvta_generic_to_shared(&Bs[0][r0 * STR + roff]);
    const uint32_t sb1 = (uint32_t)__cvta_generic_to_shared(&Bs[0][(r0 + 64) * STR + roff]);
    const uint32_t bufstep = (uint32_t)(BM * STR * sizeof(float));

    float c[4][4][4];
#pragma unroll
    for (int i = 0; i < 4; ++i)
#pragma unroll
        for (int j = 0; j < 4; ++j)
#pragma unroll
            for (int r = 0; r < 4; ++r) c[i][j][r] = 0.f;

    const int nk = K / BKK;

    auto load_tile = [&](int buf, int kc) {
        const int k0 = kc * BKK;
        const uint32_t bo = buf * bufstep;
        asm volatile("cp.async.cg.shared.global [%0], [%1], 16;\n" :: "r"(sa0 + bo), "l"(arow0 + k0) : "memory");
        asm volatile("cp.async.cg.shared.global [%0], [%1], 16;\n" :: "r"(sa1 + bo), "l"(arow1 + k0) : "memory");
        asm volatile("cp.async.cg.shared.global [%0], [%1], 16;\n" :: "r"(sb0 + bo), "l"(brow0 + k0) : "memory");
        asm volatile("cp.async.cg.shared.global [%0], [%1], 16;\n" :: "r"(sb1 + bo), "l"(brow1 + k0) : "memory");
        asm volatile("cp.async.commit_group;\n" ::: "memory");
    };

    load_tile(0, 0);

    for (int kc = 0; kc < nk; ++kc) {
        asm volatile("cp.async.wait_group 0;\n" ::: "memory");
        __syncthreads();
        if (kc + 1 < nk) load_tile((kc + 1) & 1, kc + 1);
        const int buf = kc & 1;

#pragma unroll
        for (int kk = 0; kk < BKK; kk += 8) {
            uint32_t a[4][4], b[4][2];
#pragma unroll
            for (int mi = 0; mi < 4; ++mi) {
                int r = wm + mi * 16 + g;
                a[mi][0] = __float_as_uint(As[buf][(r    ) * STR + kk + tg    ]);
                a[mi][1] = __float_as_uint(As[buf][(r + 8) * STR + kk + tg    ]);
                a[mi][2] = __float_as_uint(As[buf][(r    ) * STR + kk + tg + 4]);
                a[mi][3] = __float_as_uint(As[buf][(r + 8) * STR + kk + tg + 4]);
            }
#pragma unroll
            for (int ni = 0; ni < 4; ++ni) {
                int r = wn + ni * 8 + g;
                b[ni][0] = __float_as_uint(Bs[buf][r * STR + kk + tg    ]);
                b[ni][1] = __float_as_uint(Bs[buf][r * STR + kk + tg + 4]);
            }
#pragma unroll
            for (int mi = 0; mi < 4; ++mi)
#pragma unroll
                for (int ni = 0; ni < 4; ++ni)
                    asm volatile(
                        "mma.sync.aligned.m16n8k8.row.col.f32.tf32.tf32.f32 "
                        "{%0,%1,%2,%3}, {%4,%5,%6,%7}, {%8,%9}, {%0,%1,%2,%3};"
                        : "+f"(c[mi][ni][0]), "+f"(c[mi][ni][1]),
                          "+f"(c[mi][ni][2]), "+f"(c[mi][ni][3])
                        : "r"(a[mi][0]), "r"(a[mi][1]), "r"(a[mi][2]), "r"(a[mi][3]),
                          "r"(b[ni][0]), "r"(b[ni][1]));
        }
        __syncthreads();
    }

#pragma unroll
    for (int mi = 0; mi < 4; ++mi) {
        int m0 = blockIdx.y * BM + wm + mi * 16 + g;
        int m1 = m0 + 8;
#pragma unroll
        for (int ni = 0; ni < 4; ++ni) {
            int n0 = blockIdx.x * BN + wn + ni * 8 + 2 * tg;
            if (m0 < M) {
                float* p = C + (size_t)m0 * N + n0;
                p[0] = c[mi][ni][0]; p[1] = c[mi][ni][1];
            }
            if (m1 < M) {
                float* p = C + (size_t)m1 * N + n0;
                p[0] = c[mi][ni][2]; p[1] = c[mi][ni][3];
            }
        }
    }
}

// ---------------------------------------------------------------------------
// Sparse fused conv + bias + silu(x)*silu(z)*comb, tf32-round the output.
// Batched over experts via blockIdx.y.
// ---------------------------------------------------------------------------
__global__ void conv_act_sparse(const float* __restrict__ cw_all,   // [E][DI][4]
                                const float* __restrict__ cb_all)   // [E][DI]
{
    const int e = blockIdx.y;
    const int cnt = g_cnts2[2 * e];
    const int total = cnt * (DI / 4);
    const int* sel = g_lists + (2 * e) * NT;
    const int* posx = g_posx + e * NT;
    const float* zb = g_zx + (size_t)(2 * e) * NT * DI;
    const float* xb = g_zx + (size_t)(2 * e + 1) * NT * DI;
    float* xact = g_xact + (size_t)e * NT * DI;
    const float4* cwf = reinterpret_cast<const float4*>(cw_all + (size_t)e * DI * 4);
    const float4* cbf = reinterpret_cast<const float4*>(cb_all + (size_t)e * DI);

    for (int idx = blockIdx.x * blockDim.x + threadIdx.x; idx < total;
         idx += gridDim.x * blockDim.x) {
        const int i  = idx >> 9;           // DI/4 = 512
        const int c4 = idx & 511;
        const int c  = c4 * 4;
        const int t  = sel[i];
        const float wgt = g_comb[(size_t)t * NE + e];
        const int b = t >> 11, s = t & (Ss - 1);

        float4 w0 = cwf[c4 * 4 + 0];
        float4 w1 = cwf[c4 * 4 + 1];
        float4 w2 = cwf[c4 * 4 + 2];
        float4 w3 = cwf[c4 * 4 + 3];
        float4 acc = cbf[c4];

#pragma unroll
        for (int j = 0; j < 4; ++j) {
            int sj = s - 3 + j;
            if (sj < 0) continue;
            int r = posx[b * Ss + sj];
            const float4 xv = *reinterpret_cast<const float4*>(xb + (size_t)r * DI + c);
            float t0 = (j == 0) ? w0.x : (j == 1) ? w0.y : (j == 2) ? w0.z : w0.w;
            float t1 = (j == 0) ? w1.x : (j == 1) ? w1.y : (j == 2) ? w1.z : w1.w;
            float t2 = (j == 0) ? w2.x : (j == 1) ? w2.y : (j == 2) ? w2.z : w2.w;
            float t3 = (j == 0) ? w3.x : (j == 1) ? w3.y : (j == 2) ? w3.z : w3.w;
            acc.x += t0 * xv.x; acc.y += t1 * xv.y;
            acc.z += t2 * xv.z; acc.w += t3 * xv.w;
        }

        const float4 z = *reinterpret_cast<const float4*>(zb + (size_t)i * DI + c);
        float4 o;
        o.x = round_tf32f(silu_(acc.x) * silu_(z.x) * wgt);
        o.y = round_tf32f(silu_(acc.y) * silu_(z.y) * wgt);
        o.z = round_tf32f(silu_(acc.z) * silu_(z.z) * wgt);
        o.w = round_tf32f(silu_(acc.w) * silu_(z.w) * wgt);
        *reinterpret_cast<float4*>(xact + (size_t)i * DI + c) = o;
    }
}

// ---------------------------------------------------------------------------
// Combine: out[t] = outbuf[e1][q1] + outbuf[e2][q2].
// ---------------------------------------------------------------------------
__global__ void combine_kernel(float* __restrict__ out)
{
    const int t = blockIdx.x;
    const int4 m = g_tokmap[t];
    const float4* a = reinterpret_cast<const float4*>(
        g_outbuf + ((size_t)m.x * NT + m.y) * Dd);
    const float4* b = reinterpret_cast<const float4*>(
        g_outbuf + ((size_t)m.z * NT + m.w) * Dd);
    float4* o = reinterpret_cast<float4*>(out + (size_t)t * Dd);
    const int i = threadIdx.x;  // 256 threads x float4 = 1024 floats
    float4 va = a[i], vb = b[i];
    o[i] = make_float4(va.x + vb.x, va.y + vb.y, va.z + vb.z, va.w + vb.w);
}

// ---------------------------------------------------------------------------
extern "C" void kernel_launch(void* const* d_in, const int* in_sizes, int n_in,
                              void* d_out, int out_size)
{
    const float* h   = (const float*)d_in[0];   // [B,S,D]
    const float* inw = (const float*)d_in[1];   // [E, 2*DI, D]
    const float* cw  = (const float*)d_in[2];   // [E, DI, 1, 4]
    const float* cb  = (const float*)d_in[3];   // [E, DI]
    const float* ow  = (const float*)d_in[4];   // [E, D, DI]
    const float* rw1 = (const float*)d_in[5];   // [128, D]
    const float* rw2 = (const float*)d_in[6];   // [E, 128]
    float* out = (float*)d_out;                 // [B,S,D]

    void *zxp, *xap, *obp, *hrp, *iwp, *owp, *rhp, *cntp, *lstp;
    cudaGetSymbolAddress(&zxp, g_zx);
    cudaGetSymbolAddress(&xap, g_xact);
    cudaGetSymbolAddress(&obp, g_outbuf);
    cudaGetSymbolAddress(&hrp, g_hr);
    cudaGetSymbolAddress(&iwp, g_inwr);
    cudaGetSymbolAddress(&owp, g_owr);
    cudaGetSymbolAddress(&rhp, g_rh);
    cudaGetSymbolAddress(&cntp, g_cnts2);
    cudaGetSymbolAddress(&lstp, g_lists);
    float* zx   = (float*)zxp;
    float* xact = (float*)xap;
    float* obuf = (float*)obp;
    float* hr   = (float*)hrp;
    float* inwr = (float*)iwp;
    float* owr  = (float*)owp;
    float* rh   = (float*)rhp;
    int* cnts   = (int*)cntp;
    int* lists  = (int*)lstp;

    cudaMemsetAsync(cnts, 0, 16 * sizeof(int));

    // tf32-round all MMA inputs once (bit-identical to per-element cvt)
    round_pass<<<1024, 256>>>((const float4*)h,   (float4*)hr,   NT * Dd / 4);
    round_pass<<<2048, 256>>>((const float4*)inw, (float4*)inwr, NE * 2 * DI * Dd / 4);
    round_pass<<<2048, 256>>>((const float4*)ow,  (float4*)owr,  NE * Dd * DI / 4);

    // router, all fp32
    router_l1<<<NT / 64, 256>>>(h, rw1, rh);
    router_finish<<<(NT * 32) / 256, 256>>>(rh, rw2);
    build_xlists<<<dim3(NT / 256, NE), 256>>>();

    // in_proj: 16 jobs (expert e: job 2e = z rows, job 2e+1 = x rows)
    gemm_tn_v3<<<dim3(DI / BN, NT / BM, 16), 256>>>(
        hr, inwr, zx, cnts, 0, 1, DI, Dd,
        (size_t)0, (size_t)DI * Dd, (size_t)NT * DI, lists, (size_t)NT);

    // conv + gate, batched over experts
    conv_act_sparse<<<dim3(1024, NE), 256>>>(cw, cb);

    // out_proj per expert -> list-ordered outbuf
    gemm_tn_v3<<<dim3(Dd / BN, NT / BM, NE), 256>>>(
        xact, owr, obuf, cnts, 0, 2, Dd, DI,
        (size_t)NT * DI, (size_t)Dd * DI, (size_t)NT * Dd, nullptr, (size_t)0);

    // final combine (2 experts per token, deterministic)
    combine_kernel<<<NT, 256>>>(out);
}